// round 9
// baseline (speedup 1.0000x reference)
#include <cuda_runtime.h>
#include <math.h>

// Shapes
#define BATCH 512
#define SIG   512
#define HID   1024
#define EDGE  512
#define SLOTS 256
#define MEM   512
#define IOC   256
#define GRP   32
#define CATK  (EDGE + GRP)   // 544

// ---------------- scratch (single __device__ symbol, offsets in floats) ----
#define OFF_LAT1   0
#define OFF_READY  524288
#define OFF_QUERY  786432
#define OFF_LOGITS 1048576
#define OFF_VALUE  1179648
#define OFF_READ   1441792
#define OFF_GATE   1703936
#define OFF_CAT    1704448
#define OFF_H      1982976
#define OFF_ADAPT  2245120
#define OFF_UV     2507264
#define OFF_P      3031552
#define OFF_R      3162624
#define SCRATCH_FLOATS 3424768

__device__ float g_scratch[SCRATCH_FLOATS];

// Output layout (flat concat, reference return order)
#define OUT_LATENT  0
#define OUT_REFINED 524288
#define OUT_ENERGY  786432
#define OUT_IO      786944
#define OUT_NEWMEM  918016
#define OUT_WEIGHTS 68026880

// ---------------------------------------------------------------------------
__device__ __forceinline__ float sigmoidf_(float x) { return 1.0f / (1.0f + expf(-x)); }
__device__ __forceinline__ float siluf_(float x)    { return x / (1.0f + expf(-x)); }

__device__ __forceinline__ float blockReduceSum(float v) {
    __shared__ float sh[33];
    __syncthreads();
    int lane = threadIdx.x & 31, wid = threadIdx.x >> 5;
    #pragma unroll
    for (int o = 16; o > 0; o >>= 1) v += __shfl_down_sync(0xffffffffu, v, o);
    if (lane == 0) sh[wid] = v;
    __syncthreads();
    int nw = (blockDim.x + 31) >> 5;
    if (wid == 0) {
        float w = (lane < nw) ? sh[lane] : 0.0f;
        #pragma unroll
        for (int o = 16; o > 0; o >>= 1) w += __shfl_down_sync(0xffffffffu, w, o);
        if (lane == 0) sh[32] = w;
    }
    __syncthreads();
    return sh[32];
}

__device__ __forceinline__ float blockReduceMax(float v) {
    __shared__ float sh[33];
    __syncthreads();
    int lane = threadIdx.x & 31, wid = threadIdx.x >> 5;
    #pragma unroll
    for (int o = 16; o > 0; o >>= 1) v = fmaxf(v, __shfl_down_sync(0xffffffffu, v, o));
    if (lane == 0) sh[wid] = v;
    __syncthreads();
    int nw = (blockDim.x + 31) >> 5;
    if (wid == 0) {
        float w = (lane < nw) ? sh[lane] : -3.4e38f;
        #pragma unroll
        for (int o = 16; o > 0; o >>= 1) w = fmaxf(w, __shfl_down_sync(0xffffffffu, w, o));
        if (lane == 0) sh[32] = w;
    }
    __syncthreads();
    return sh[32];
}

// ---------------------------------------------------------------------------
// 3xTF32 tensor-core GEMM with fused epilogue:
//   C[M,N] = act(A[M,K] @ W[N,K]^T + bias + addend)
// BM=32, BN=64, BK=16, 256 threads (8 warps as 2m x 4n, each 16x16).
// fp32 accuracy via hi/lo tf32 split: hi*hi + hi*lo + lo*hi.
// Requires M mult 32, N mult 64, K mult 16, rows 16B-aligned.
__device__ __forceinline__ unsigned f2tf32(float f) {
    unsigned u;
    asm("cvt.rna.tf32.f32 %0, %1;" : "=r"(u) : "f"(f));
    return u;
}

__device__ __forceinline__ void mma_tf32(float c[4], const unsigned a[4], const unsigned b[2]) {
    asm("mma.sync.aligned.m16n8k8.row.col.f32.tf32.tf32.f32 "
        "{%0,%1,%2,%3}, {%4,%5,%6,%7}, {%8,%9}, {%0,%1,%2,%3};\n"
        : "+f"(c[0]), "+f"(c[1]), "+f"(c[2]), "+f"(c[3])
        : "r"(a[0]), "r"(a[1]), "r"(a[2]), "r"(a[3]), "r"(b[0]), "r"(b[1]));
}

#define SMPITCH 20   // bank-conflict-free pitch

struct GemmSmem {
    float Ah[32][SMPITCH];
    float Al[32][SMPITCH];
    float Bh[64][SMPITCH];
    float Bl[64][SMPITCH];
};

__device__ __forceinline__ void gemm_core(GemmSmem& sm,
                                          const float* __restrict__ A,
                                          const float* __restrict__ W,
                                          int byM, int bxN, int K,
                                          float cacc[2][4]) {
    const int tid = threadIdx.x;
    const int lane = tid & 31;
    const int warp = tid >> 5;
    const int wm = (warp >> 2) << 4;     // 0 or 16
    const int wn = (warp & 3) << 4;      // 0,16,32,48
    const int r4 = lane >> 2;            // 0..7
    const int c4 = lane & 3;             // 0..3

    // staging: all 256 threads own one float4 of B tile (64x16);
    // threads <128 also own one float4 of A tile (32x16)
    const int brow = tid >> 2;           // 0..63
    const int bc4  = (tid & 3) << 2;
    const int arow = (tid >> 2) & 31;    // 0..31 (only tid<128 used)
    const int ac4  = bc4;

    const float* Aptr = A + (size_t)(byM + arow) * K + ac4;
    const float* Wptr = W + (size_t)(bxN + brow) * K + bc4;

    #pragma unroll
    for (int ni = 0; ni < 2; ni++)
        #pragma unroll
        for (int r = 0; r < 4; r++) cacc[ni][r] = 0.0f;

    float4 av = make_float4(0.f,0.f,0.f,0.f);
    if (tid < 128) av = *reinterpret_cast<const float4*>(Aptr);
    float4 wv = *reinterpret_cast<const float4*>(Wptr);

    for (int kt = 0; kt < K; kt += 16) {
        if (tid < 128) {
            float va[4] = {av.x, av.y, av.z, av.w};
            float h[4], l[4];
            #pragma unroll
            for (int i = 0; i < 4; i++) {
                h[i] = __uint_as_float(f2tf32(va[i]));
                l[i] = __uint_as_float(f2tf32(va[i] - h[i]));
            }
            *reinterpret_cast<float4*>(&sm.Ah[arow][ac4]) = make_float4(h[0], h[1], h[2], h[3]);
            *reinterpret_cast<float4*>(&sm.Al[arow][ac4]) = make_float4(l[0], l[1], l[2], l[3]);
        }
        {
            float vw[4] = {wv.x, wv.y, wv.z, wv.w};
            float h[4], l[4];
            #pragma unroll
            for (int i = 0; i < 4; i++) {
                h[i] = __uint_as_float(f2tf32(vw[i]));
                l[i] = __uint_as_float(f2tf32(vw[i] - h[i]));
            }
            *reinterpret_cast<float4*>(&sm.Bh[brow][bc4]) = make_float4(h[0], h[1], h[2], h[3]);
            *reinterpret_cast<float4*>(&sm.Bl[brow][bc4]) = make_float4(l[0], l[1], l[2], l[3]);
        }
        __syncthreads();

        if (kt + 16 < K) {               // prefetch next tile
            if (tid < 128) av = *reinterpret_cast<const float4*>(Aptr + kt + 16);
            wv = *reinterpret_cast<const float4*>(Wptr + kt + 16);
        }

        #pragma unroll
        for (int ks = 0; ks < 16; ks += 8) {
            unsigned ah[4], al[4], bh[2][2], bl[2][2];
            ah[0] = __float_as_uint(sm.Ah[wm + r4    ][ks + c4    ]);
            ah[1] = __float_as_uint(sm.Ah[wm + r4 + 8][ks + c4    ]);
            ah[2] = __float_as_uint(sm.Ah[wm + r4    ][ks + c4 + 4]);
            ah[3] = __float_as_uint(sm.Ah[wm + r4 + 8][ks + c4 + 4]);
            al[0] = __float_as_uint(sm.Al[wm + r4    ][ks + c4    ]);
            al[1] = __float_as_uint(sm.Al[wm + r4 + 8][ks + c4    ]);
            al[2] = __float_as_uint(sm.Al[wm + r4    ][ks + c4 + 4]);
            al[3] = __float_as_uint(sm.Al[wm + r4 + 8][ks + c4 + 4]);
            #pragma unroll
            for (int ni = 0; ni < 2; ni++) {
                int nb = wn + ni * 8 + r4;
                bh[ni][0] = __float_as_uint(sm.Bh[nb][ks + c4    ]);
                bh[ni][1] = __float_as_uint(sm.Bh[nb][ks + c4 + 4]);
                bl[ni][0] = __float_as_uint(sm.Bl[nb][ks + c4    ]);
                bl[ni][1] = __float_as_uint(sm.Bl[nb][ks + c4 + 4]);
            }
            // pass-reordered: 2 independent accumulators per pass
            #pragma unroll
            for (int ni = 0; ni < 2; ni++) mma_tf32(cacc[ni], ah, bh[ni]);
            #pragma unroll
            for (int ni = 0; ni < 2; ni++) mma_tf32(cacc[ni], ah, bl[ni]);
            #pragma unroll
            for (int ni = 0; ni < 2; ni++) mma_tf32(cacc[ni], al, bh[ni]);
        }
        __syncthreads();
    }
}

template<int ACT>
__device__ __forceinline__ void gemm_epilogue(const float cacc[2][4],
                                              const float* __restrict__ bias,
                                              const float* __restrict__ addend,
                                              float* __restrict__ C,
                                              int byM, int bxN, int N) {
    const int tid = threadIdx.x;
    const int lane = tid & 31;
    const int warp = tid >> 5;
    const int wm = (warp >> 2) << 4;
    const int wn = (warp & 3) << 4;
    const int r4 = lane >> 2;
    const int c4 = lane & 3;

    #pragma unroll
    for (int ni = 0; ni < 2; ni++) {
        int col0 = bxN + wn + ni * 8 + c4 * 2;
        #pragma unroll
        for (int half = 0; half < 2; half++) {
            int row = byM + wm + r4 + half * 8;
            float v0 = cacc[ni][half * 2 + 0];
            float v1 = cacc[ni][half * 2 + 1];
            if (bias)   { v0 += bias[col0]; v1 += bias[col0 + 1]; }
            if (addend) {
                const float* ad = addend + (size_t)row * N + col0;
                v0 += ad[0]; v1 += ad[1];
            }
            if (ACT == 1) { v0 = siluf_(v0); v1 = siluf_(v1); }
            if (ACT == 2) { v0 = sigmoidf_(v0); v1 = sigmoidf_(v1); }
            *reinterpret_cast<float2*>(C + (size_t)row * N + col0) = make_float2(v0, v1);
        }
    }
}

template<int ACT>
__global__ void __launch_bounds__(256, 2)
gemm_tf32_kernel(const float* __restrict__ A,
                 const float* __restrict__ W,
                 const float* __restrict__ bias,
                 const float* __restrict__ addend,
                 float* __restrict__ C,
                 int M, int N, int K) {
    __shared__ GemmSmem sm;
    float cacc[2][4];
    gemm_core(sm, A, W, blockIdx.y * 32, blockIdx.x * 64, K, cacc);
    gemm_epilogue<ACT>(cacc, bias, addend, C, blockIdx.y * 32, blockIdx.x * 64, N);
}

// z-batched trio sharing A=o_latent, M=BATCH, N=512, K=HID:
//   z=0: readiness = sigmoid(A@edge_w^T + edge_b)
//   z=1: query     =          A@rq_w^T   + rq_b
//   z=2: value     =          A@wv_w^T   + wv_b
__global__ void __launch_bounds__(256, 2)
gemm3_kernel(const float* __restrict__ A,
             const float* __restrict__ edge_w, const float* __restrict__ edge_b,
             const float* __restrict__ rq_w,   const float* __restrict__ rq_b,
             const float* __restrict__ wv_w,   const float* __restrict__ wv_b,
             float* __restrict__ readiness, float* __restrict__ query,
             float* __restrict__ value) {
    __shared__ GemmSmem sm;
    float cacc[2][4];
    const float* W;
    const float* bias;
    float* C;
    if (blockIdx.z == 0)      { W = edge_w; bias = edge_b; C = readiness; }
    else if (blockIdx.z == 1) { W = rq_w;   bias = rq_b;   C = query; }
    else                      { W = wv_w;   bias = wv_b;   C = value; }
    gemm_core(sm, A, W, blockIdx.y * 32, blockIdx.x * 64, HID, cacc);
    if (blockIdx.z == 0)
        gemm_epilogue<2>(cacc, bias, nullptr, C, blockIdx.y * 32, blockIdx.x * 64, EDGE);
    else
        gemm_epilogue<0>(cacc, bias, nullptr, C, blockIdx.y * 32, blockIdx.x * 64, MEM);
}

// ---------------------------------------------------------------------------
// Fused per-row memory block: softmax(logits) -> weights, read, gate, energy.
__global__ void fused_mem_kernel(const float* __restrict__ logits,
                                 const float* __restrict__ memory,
                                 const float* __restrict__ latent,
                                 const float* __restrict__ wg,
                                 const float* __restrict__ wgb,
                                 const float* __restrict__ ew,
                                 const float* __restrict__ eb,
                                 float* __restrict__ weights_out,
                                 float* __restrict__ readv,
                                 float* __restrict__ gate,
                                 float* __restrict__ energy) {
    __shared__ float wsh[SLOTS];
    int b = blockIdx.x;
    int tid = threadIdx.x;

    float x = logits[(size_t)b * SLOTS + tid];
    float m = blockReduceMax(x);
    float e = expf(x - m);
    float ssum = blockReduceSum(e);
    float w = e / ssum;
    weights_out[(size_t)b * SLOTS + tid] = w;
    wsh[tid] = w;
    __syncthreads();

    float4 acc = make_float4(0.f, 0.f, 0.f, 0.f);
    if (tid < MEM / 4) {
        const float4* mb = reinterpret_cast<const float4*>(memory + (size_t)b * SLOTS * MEM);
        #pragma unroll 4
        for (int s = 0; s < SLOTS; s++) {
            float ws = wsh[s];
            float4 mv = mb[(size_t)s * (MEM / 4) + tid];
            acc.x = fmaf(ws, mv.x, acc.x);
            acc.y = fmaf(ws, mv.y, acc.y);
            acc.z = fmaf(ws, mv.z, acc.z);
            acc.w = fmaf(ws, mv.w, acc.w);
        }
        reinterpret_cast<float4*>(readv + (size_t)b * MEM)[tid] = acc;
    }

    float g = 0.0f, en = 0.0f;
    if (tid < MEM / 4) {
        float4 wv = reinterpret_cast<const float4*>(wg + HID)[tid];
        g = acc.x * wv.x + acc.y * wv.y + acc.z * wv.z + acc.w * wv.w;
    }
    const float4* lx = reinterpret_cast<const float4*>(latent + (size_t)b * HID);
    const float4* w1 = reinterpret_cast<const float4*>(wg);
    const float4* ev = reinterpret_cast<const float4*>(ew);
    for (int i = tid; i < HID / 4; i += blockDim.x) {
        float4 xv = lx[i], gv = w1[i], eV = ev[i];
        g  += xv.x * gv.x + xv.y * gv.y + xv.z * gv.z + xv.w * gv.w;
        en += xv.x * eV.x + xv.y * eV.y + xv.z * eV.z + xv.w * eV.w;
    }
    g  = blockReduceSum(g);
    en = blockReduceSum(en);
    if (tid == 0) {
        gate[b]   = sigmoidf_(g + wgb[0]);
        energy[b] = fmaxf(en + eb[0], 0.0f);
    }
}

// new_memory[b,s,d] = m + gate[b]*w[b,s]*(value[b,d] - m), float4 over d
__global__ void newmem_kernel(const float* __restrict__ memory,
                              const float* __restrict__ weights,
                              const float* __restrict__ gate,
                              const float* __restrict__ value,
                              float* __restrict__ out) {
    size_t idx = (size_t)blockIdx.x * blockDim.x + threadIdx.x;  // float4 index
    int b   = (int)(idx >> 15);           // SLOTS*MEM/4 = 32768 per batch
    int rem = (int)(idx & 32767);
    int s   = rem >> 7;                   // MEM/4 = 128
    int d4  = rem & 127;
    float gw = gate[b] * weights[(size_t)b * SLOTS + s];
    float4 m = reinterpret_cast<const float4*>(memory)[idx];
    float4 v = reinterpret_cast<const float4*>(value)[(size_t)b * 128 + d4];
    float4 o;
    o.x = fmaf(gw, v.x - m.x, m.x);
    o.y = fmaf(gw, v.y - m.y, m.y);
    o.z = fmaf(gw, v.z - m.z, m.z);
    o.w = fmaf(gw, v.w - m.w, m.w);
    reinterpret_cast<float4*>(out)[idx] = o;
}

// cat[b, 0:512] = refined[b,:], cat[b, 512:544] = remap[b,:]
__global__ void concat_kernel(const float* __restrict__ refined,
                              const float* __restrict__ remap,
                              float* __restrict__ cat) {
    int idx = blockIdx.x * blockDim.x + threadIdx.x;
    if (idx >= BATCH * CATK) return;
    int b = idx / CATK, c = idx - b * CATK;
    cat[idx] = (c < EDGE) ? refined[(size_t)b * EDGE + c]
                          : remap[(size_t)b * GRP + (c - EDGE)];
}

// P = exp(base_map), elementwise
__global__ void expP_kernel(const float* __restrict__ base_map,
                            float* __restrict__ P) {
    int idx = blockIdx.x * blockDim.x + threadIdx.x;
    P[idx] = expf(base_map[idx]);
}

// UV[b,:]     = exp(adapt[b,:] - rowmax)
// UV[512+b,:] = exp(adapt[b,:] - rowmax) * refined[b,:]
__global__ void uv_kernel(const float* __restrict__ adapt,
                          const float* __restrict__ refined,
                          float* __restrict__ UV) {
    int b = blockIdx.x;
    int e = threadIdx.x;          // 512 threads
    float x = adapt[(size_t)b * EDGE + e];
    float m = blockReduceMax(x);
    float u = expf(x - m);
    UV[(size_t)b * EDGE + e] = u;
    UV[(size_t)(BATCH + b) * EDGE + e] = u * refined[(size_t)b * EDGE + e];
}

// io[b,c] = R[512+b,c] / R[b,c]
__global__ void io_kernel(const float* __restrict__ R,
                          float* __restrict__ io) {
    int idx = blockIdx.x * blockDim.x + threadIdx.x;
    int b = idx >> 8, c = idx & 255;
    io[idx] = R[(size_t)(BATCH + b) * IOC + c] / R[(size_t)b * IOC + c];
}

// ---------------------------------------------------------------------------
static inline void gemm_tc(const float* A, const float* W, const float* bias,
                           const float* addend, float* C,
                           int M, int N, int K, int act) {
    dim3 grid(N / 64, M / 32);
    if (act == 0)      gemm_tf32_kernel<0><<<grid, 256>>>(A, W, bias, addend, C, M, N, K);
    else if (act == 1) gemm_tf32_kernel<1><<<grid, 256>>>(A, W, bias, addend, C, M, N, K);
    else               gemm_tf32_kernel<2><<<grid, 256>>>(A, W, bias, addend, C, M, N, K);
}

extern "C" void kernel_launch(void* const* d_in, const int* in_sizes, int n_in,
                              void* d_out, int out_size) {
    const float* signal     = (const float*)d_in[0];
    const float* memory     = (const float*)d_in[1];
    const float* remap_code = (const float*)d_in[2];
    const float* enc_w1     = (const float*)d_in[3];
    const float* enc_b1     = (const float*)d_in[4];
    const float* enc_w2     = (const float*)d_in[5];
    const float* enc_b2     = (const float*)d_in[6];
    const float* edge_w     = (const float*)d_in[7];
    const float* edge_b     = (const float*)d_in[8];
    const float* energy_w   = (const float*)d_in[9];
    const float* energy_b   = (const float*)d_in[10];
    const float* rq_w       = (const float*)d_in[11];
    const float* rq_b       = (const float*)d_in[12];
    const float* wg_w       = (const float*)d_in[13];
    const float* wg_b       = (const float*)d_in[14];
    const float* wv_w       = (const float*)d_in[15];
    const float* wv_b       = (const float*)d_in[16];
    const float* memory_key = (const float*)d_in[17];
    const float* m2e_w      = (const float*)d_in[18];
    const float* m2e_b      = (const float*)d_in[19];
    const float* base_map   = (const float*)d_in[20];
    const float* a1_w       = (const float*)d_in[21];
    const float* a1_b       = (const float*)d_in[22];
    const float* a2_w       = (const float*)d_in[23];
    const float* a2_b       = (const float*)d_in[24];

    float* out = (float*)d_out;
    float* o_latent  = out + OUT_LATENT;
    float* o_refined = out + OUT_REFINED;
    float* o_energy  = out + OUT_ENERGY;
    float* o_io      = out + OUT_IO;
    float* o_newmem  = out + OUT_NEWMEM;
    float* o_weights = out + OUT_WEIGHTS;

    float* scratch = nullptr;
    cudaGetSymbolAddress((void**)&scratch, g_scratch);
    float* lat1      = scratch + OFF_LAT1;
    float* readiness = scratch + OFF_READY;
    float* query     = scratch + OFF_QUERY;
    float* logits    = scratch + OFF_LOGITS;
    float* value     = scratch + OFF_VALUE;
    float* readv     = scratch + OFF_READ;
    float* gate      = scratch + OFF_GATE;
    float* cat       = scratch + OFF_CAT;
    float* hmid      = scratch + OFF_H;
    float* adapt     = scratch + OFF_ADAPT;
    float* UV        = scratch + OFF_UV;
    float* P         = scratch + OFF_P;
    float* R         = scratch + OFF_R;

    // 1-2: encoder (256 CTAs each)
    gemm_tc(signal, enc_w1, enc_b1, nullptr, lat1,     BATCH, HID, SIG, 1);
    gemm_tc(lat1,   enc_w2, enc_b2, nullptr, o_latent, BATCH, HID, HID, 1);

    // 3: readiness + query + value in ONE launch (384 CTAs)
    gemm3_kernel<<<dim3(EDGE / 64, BATCH / 32, 3), 256>>>(
        o_latent, edge_w, edge_b, rq_w, rq_b, wv_w, wv_b,
        readiness, query, value);

    // 4: logits
    gemm_tc(query, memory_key, nullptr, nullptr, logits, BATCH, SLOTS, MEM, 0);

    // 5: fused softmax/read/gate/energy
    fused_mem_kernel<<<BATCH, 256>>>(logits, memory, o_latent, wg_w, wg_b,
                                     energy_w, energy_b,
                                     o_weights, readv, gate, o_energy);

    // 6: new_memory
    newmem_kernel<<<(BATCH*SLOTS*MEM/4)/256, 256>>>(memory, o_weights, gate, value, o_newmem);

    // 7: refined = sigmoid(readiness + read@m2e^T + m2e_b)
    gemm_tc(readv, m2e_w, m2e_b, readiness, o_refined, BATCH, EDGE, MEM, 2);

    // 8-10: router MLP
    concat_kernel<<<(BATCH*CATK + 255)/256, 256>>>(o_refined, remap_code, cat);
    gemm_tc(cat,  a1_w, a1_b, nullptr, hmid,  BATCH, EDGE, CATK, 1);
    gemm_tc(hmid, a2_w, a2_b, nullptr, adapt, BATCH, EDGE, EDGE, 0);

    // 11-14: factorized io softmax
    expP_kernel<<<(IOC*EDGE)/256, 256>>>(base_map, P);
    uv_kernel<<<BATCH, EDGE>>>(adapt, o_refined, UV);
    gemm_tc(UV, P, nullptr, nullptr, R, 2*BATCH, IOC, EDGE, 0);
    io_kernel<<<(BATCH*IOC)/256, 256>>>(R, o_io);
}

// round 11
// speedup vs baseline: 1.0434x; 1.0434x over previous
#include <cuda_runtime.h>
#include <math.h>

// Shapes
#define BATCH 512
#define SIG   512
#define HID   1024
#define EDGE  512
#define SLOTS 256
#define MEM   512
#define IOC   256
#define GRP   32
#define CATK  (EDGE + GRP)   // 544

// ---------------- scratch (single __device__ symbol, offsets in floats) ----
#define OFF_LAT1   0
#define OFF_READY  524288
#define OFF_QUERY  786432
#define OFF_LOGITS 1048576
#define OFF_VALUE  1179648
#define OFF_READ   1441792
#define OFF_GATE   1703936
#define OFF_CAT    1704448
#define OFF_H      1982976
#define OFF_ADAPT  2245120
#define OFF_UV     2507264
#define OFF_P      3031552
#define OFF_R      3162624
#define OFF_PART   3424768            // up to 2M floats of split-K partials
#define SCRATCH_FLOATS (OFF_PART + 2097152)

__device__ float g_scratch[SCRATCH_FLOATS];
__device__ int   g_cnt[1024];         // per-tile semaphores; self-cleaning to 0

// Output layout (flat concat, reference return order)
#define OUT_LATENT  0
#define OUT_REFINED 524288
#define OUT_ENERGY  786432
#define OUT_IO      786944
#define OUT_NEWMEM  918016
#define OUT_WEIGHTS 68026880

// ---------------------------------------------------------------------------
__device__ __forceinline__ float sigmoidf_(float x) { return 1.0f / (1.0f + expf(-x)); }
__device__ __forceinline__ float siluf_(float x)    { return x / (1.0f + expf(-x)); }

__device__ __forceinline__ float blockReduceSum(float v) {
    __shared__ float sh[33];
    __syncthreads();
    int lane = threadIdx.x & 31, wid = threadIdx.x >> 5;
    #pragma unroll
    for (int o = 16; o > 0; o >>= 1) v += __shfl_down_sync(0xffffffffu, v, o);
    if (lane == 0) sh[wid] = v;
    __syncthreads();
    int nw = (blockDim.x + 31) >> 5;
    if (wid == 0) {
        float w = (lane < nw) ? sh[lane] : 0.0f;
        #pragma unroll
        for (int o = 16; o > 0; o >>= 1) w += __shfl_down_sync(0xffffffffu, w, o);
        if (lane == 0) sh[32] = w;
    }
    __syncthreads();
    return sh[32];
}

__device__ __forceinline__ float blockReduceMax(float v) {
    __shared__ float sh[33];
    __syncthreads();
    int lane = threadIdx.x & 31, wid = threadIdx.x >> 5;
    #pragma unroll
    for (int o = 16; o > 0; o >>= 1) v = fmaxf(v, __shfl_down_sync(0xffffffffu, v, o));
    if (lane == 0) sh[wid] = v;
    __syncthreads();
    int nw = (blockDim.x + 31) >> 5;
    if (wid == 0) {
        float w = (lane < nw) ? sh[lane] : -3.4e38f;
        #pragma unroll
        for (int o = 16; o > 0; o >>= 1) w = fmaxf(w, __shfl_down_sync(0xffffffffu, w, o));
        if (lane == 0) sh[32] = w;
    }
    __syncthreads();
    return sh[32];
}

// ---------------------------------------------------------------------------
// 3xTF32 tensor-core GEMM core (BM=32, BN=64, BK=16, 256 threads, 8 warps
// each owning a 16x16 warp tile via 2 m16n8k8 atoms). fp32 accuracy via
// hi/lo tf32 split: hi*hi + hi*lo + lo*hi.
__device__ __forceinline__ unsigned f2tf32(float f) {
    unsigned u;
    asm("cvt.rna.tf32.f32 %0, %1;" : "=r"(u) : "f"(f));
    return u;
}

__device__ __forceinline__ void mma_tf32(float c[4], const unsigned a[4], const unsigned b[2]) {
    asm("mma.sync.aligned.m16n8k8.row.col.f32.tf32.tf32.f32 "
        "{%0,%1,%2,%3}, {%4,%5,%6,%7}, {%8,%9}, {%0,%1,%2,%3};\n"
        : "+f"(c[0]), "+f"(c[1]), "+f"(c[2]), "+f"(c[3])
        : "r"(a[0]), "r"(a[1]), "r"(a[2]), "r"(a[3]), "r"(b[0]), "r"(b[1]));
}

#define SMPITCH 20   // bank-conflict-free pitch

struct GemmSmem {
    float Ah[32][SMPITCH];
    float Al[32][SMPITCH];
    float Bh[64][SMPITCH];
    float Bl[64][SMPITCH];
};

// Computes partial C tile for rows [byM,byM+32), cols [bxN,bxN+64) over
// k in [kStart, kStart+kLen). ldK = row stride of A and W.
__device__ __forceinline__ void gemm_core(GemmSmem& sm,
                                          const float* __restrict__ A,
                                          const float* __restrict__ W,
                                          int byM, int bxN, int ldK,
                                          int kStart, int kLen,
                                          float cacc[2][4]) {
    const int tid = threadIdx.x;
    const int lane = tid & 31;
    const int warp = tid >> 5;
    const int wm = (warp >> 2) << 4;     // 0 or 16
    const int wn = (warp & 3) << 4;      // 0,16,32,48
    const int r4 = lane >> 2;            // 0..7
    const int c4 = lane & 3;             // 0..3

    const int brow = tid >> 2;           // 0..63
    const int bc4  = (tid & 3) << 2;
    const int arow = (tid >> 2) & 31;    // 0..31 (tid<128 stage A)

    const float* Aptr = A + (size_t)(byM + arow) * ldK + kStart + bc4;
    const float* Wptr = W + (size_t)(bxN + brow) * ldK + kStart + bc4;

    #pragma unroll
    for (int ni = 0; ni < 2; ni++)
        #pragma unroll
        for (int r = 0; r < 4; r++) cacc[ni][r] = 0.0f;

    float4 av = make_float4(0.f,0.f,0.f,0.f);
    if (tid < 128) av = *reinterpret_cast<const float4*>(Aptr);
    float4 wv = *reinterpret_cast<const float4*>(Wptr);

    for (int kt = 0; kt < kLen; kt += 16) {
        if (tid < 128) {
            float va[4] = {av.x, av.y, av.z, av.w};
            float h[4], l[4];
            #pragma unroll
            for (int i = 0; i < 4; i++) {
                h[i] = __uint_as_float(f2tf32(va[i]));
                l[i] = __uint_as_float(f2tf32(va[i] - h[i]));
            }
            *reinterpret_cast<float4*>(&sm.Ah[arow][bc4]) = make_float4(h[0], h[1], h[2], h[3]);
            *reinterpret_cast<float4*>(&sm.Al[arow][bc4]) = make_float4(l[0], l[1], l[2], l[3]);
        }
        {
            float vw[4] = {wv.x, wv.y, wv.z, wv.w};
            float h[4], l[4];
            #pragma unroll
            for (int i = 0; i < 4; i++) {
                h[i] = __uint_as_float(f2tf32(vw[i]));
                l[i] = __uint_as_float(f2tf32(vw[i] - h[i]));
            }
            *reinterpret_cast<float4*>(&sm.Bh[brow][bc4]) = make_float4(h[0], h[1], h[2], h[3]);
            *reinterpret_cast<float4*>(&sm.Bl[brow][bc4]) = make_float4(l[0], l[1], l[2], l[3]);
        }
        __syncthreads();

        if (kt + 16 < kLen) {            // prefetch next tile
            if (tid < 128) av = *reinterpret_cast<const float4*>(Aptr + kt + 16);
            wv = *reinterpret_cast<const float4*>(Wptr + kt + 16);
        }

        #pragma unroll
        for (int ks = 0; ks < 16; ks += 8) {
            unsigned ah[4], al[4], bh[2][2], bl[2][2];
            ah[0] = __float_as_uint(sm.Ah[wm + r4    ][ks + c4    ]);
            ah[1] = __float_as_uint(sm.Ah[wm + r4 + 8][ks + c4    ]);
            ah[2] = __float_as_uint(sm.Ah[wm + r4    ][ks + c4 + 4]);
            ah[3] = __float_as_uint(sm.Ah[wm + r4 + 8][ks + c4 + 4]);
            al[0] = __float_as_uint(sm.Al[wm + r4    ][ks + c4    ]);
            al[1] = __float_as_uint(sm.Al[wm + r4 + 8][ks + c4    ]);
            al[2] = __float_as_uint(sm.Al[wm + r4    ][ks + c4 + 4]);
            al[3] = __float_as_uint(sm.Al[wm + r4 + 8][ks + c4 + 4]);
            #pragma unroll
            for (int ni = 0; ni < 2; ni++) {
                int nb = wn + ni * 8 + r4;
                bh[ni][0] = __float_as_uint(sm.Bh[nb][ks + c4    ]);
                bh[ni][1] = __float_as_uint(sm.Bh[nb][ks + c4 + 4]);
                bl[ni][0] = __float_as_uint(sm.Bl[nb][ks + c4    ]);
                bl[ni][1] = __float_as_uint(sm.Bl[nb][ks + c4 + 4]);
            }
            #pragma unroll
            for (int ni = 0; ni < 2; ni++) mma_tf32(cacc[ni], ah, bh[ni]);
            #pragma unroll
            for (int ni = 0; ni < 2; ni++) mma_tf32(cacc[ni], ah, bl[ni]);
            #pragma unroll
            for (int ni = 0; ni < 2; ni++) mma_tf32(cacc[ni], al, bh[ni]);
        }
        __syncthreads();
    }
}

template<int ACT>
__device__ __forceinline__ void gemm_epilogue(const float cacc[2][4],
                                              const float* __restrict__ bias,
                                              const float* __restrict__ addend,
                                              float* __restrict__ C,
                                              int byM, int bxN, int N) {
    const int tid = threadIdx.x;
    const int lane = tid & 31;
    const int warp = tid >> 5;
    const int wm = (warp >> 2) << 4;
    const int wn = (warp & 3) << 4;
    const int r4 = lane >> 2;
    const int c4 = lane & 3;

    #pragma unroll
    for (int ni = 0; ni < 2; ni++) {
        int col0 = bxN + wn + ni * 8 + c4 * 2;
        #pragma unroll
        for (int half = 0; half < 2; half++) {
            int row = byM + wm + r4 + half * 8;
            float v0 = cacc[ni][half * 2 + 0];
            float v1 = cacc[ni][half * 2 + 1];
            if (bias)   { v0 += bias[col0]; v1 += bias[col0 + 1]; }
            if (addend) {
                const float* ad = addend + (size_t)row * N + col0;
                v0 += ad[0]; v1 += ad[1];
            }
            if (ACT == 1) { v0 = siluf_(v0); v1 = siluf_(v1); }
            if (ACT == 2) { v0 = sigmoidf_(v0); v1 = sigmoidf_(v1); }
            *reinterpret_cast<float2*>(C + (size_t)row * N + col0) = make_float2(v0, v1);
        }
    }
}

// Split-K finish: write partial, semaphore, last CTA reduces in fixed z order
// (deterministic) and runs the fused epilogue. Counters self-clean to 0.
// Returns true only on the reducing CTA, with the summed cacc.
__device__ __forceinline__ bool splitk_finish(float cacc[2][4],
                                              float* __restrict__ part,
                                              int* __restrict__ cnt,
                                              int tile, int S, int bz) {
    __shared__ int is_last;
    float* myp = part + ((size_t)tile * S + bz) * 2048 + threadIdx.x * 8;
    *reinterpret_cast<float4*>(myp)     = make_float4(cacc[0][0], cacc[0][1], cacc[0][2], cacc[0][3]);
    *reinterpret_cast<float4*>(myp + 4) = make_float4(cacc[1][0], cacc[1][1], cacc[1][2], cacc[1][3]);
    __threadfence();
    if (threadIdx.x == 0) is_last = (atomicAdd(&cnt[tile], 1) == S - 1);
    __syncthreads();
    if (!is_last) return false;
    float4 s0 = make_float4(0.f,0.f,0.f,0.f), s1 = s0;
    const float* base = part + (size_t)tile * S * 2048 + threadIdx.x * 8;
    for (int z = 0; z < S; z++) {           // fixed order -> deterministic
        float4 p0 = *reinterpret_cast<const float4*>(base + (size_t)z * 2048);
        float4 p1 = *reinterpret_cast<const float4*>(base + (size_t)z * 2048 + 4);
        s0.x += p0.x; s0.y += p0.y; s0.z += p0.z; s0.w += p0.w;
        s1.x += p1.x; s1.y += p1.y; s1.z += p1.z; s1.w += p1.w;
    }
    cacc[0][0]=s0.x; cacc[0][1]=s0.y; cacc[0][2]=s0.z; cacc[0][3]=s0.w;
    cacc[1][0]=s1.x; cacc[1][1]=s1.y; cacc[1][2]=s1.z; cacc[1][3]=s1.w;
    if (threadIdx.x == 0) cnt[tile] = 0;    // self-clean for next GEMM / replay
    return true;
}

template<int ACT>
__global__ void __launch_bounds__(256, 2)
gemm_sk_kernel(const float* __restrict__ A,
               const float* __restrict__ W,
               const float* __restrict__ bias,
               const float* __restrict__ addend,
               float* __restrict__ C,
               float* __restrict__ part,
               int* __restrict__ cnt,
               int M, int N, int K, int S) {
    __shared__ GemmSmem sm;
    float cacc[2][4];
    int kChunk = K / S;
    gemm_core(sm, A, W, blockIdx.y * 32, blockIdx.x * 64, K,
              blockIdx.z * kChunk, kChunk, cacc);
    if (S > 1) {
        int tile = blockIdx.y * gridDim.x + blockIdx.x;
        if (!splitk_finish(cacc, part, cnt, tile, S, blockIdx.z)) return;
    }
    gemm_epilogue<ACT>(cacc, bias, addend, C, blockIdx.y * 32, blockIdx.x * 64, N);
}

// z-batched trio sharing A=o_latent (M=BATCH, N=512, K=HID), split-K S each:
//   sel=0: readiness = sigmoid(A@edge_w^T + edge_b)
//   sel=1: query     =          A@rq_w^T   + rq_b
//   sel=2: value     =          A@wv_w^T   + wv_b
__global__ void __launch_bounds__(256, 2)
gemm3_sk_kernel(const float* __restrict__ A,
                const float* __restrict__ edge_w, const float* __restrict__ edge_b,
                const float* __restrict__ rq_w,   const float* __restrict__ rq_b,
                const float* __restrict__ wv_w,   const float* __restrict__ wv_b,
                float* __restrict__ readiness, float* __restrict__ query,
                float* __restrict__ value,
                float* __restrict__ part, int* __restrict__ cnt, int S) {
    __shared__ GemmSmem sm;
    float cacc[2][4];
    int sel = blockIdx.z / S;
    int bz  = blockIdx.z - sel * S;
    const float* W;
    const float* bias;
    float* C;
    if (sel == 0)      { W = edge_w; bias = edge_b; C = readiness; }
    else if (sel == 1) { W = rq_w;   bias = rq_b;   C = query; }
    else               { W = wv_w;   bias = wv_b;   C = value; }
    int kChunk = HID / S;
    gemm_core(sm, A, W, blockIdx.y * 32, blockIdx.x * 64, HID, bz * kChunk, kChunk, cacc);
    if (S > 1) {
        int ntile = gridDim.x * gridDim.y;
        int tile = sel * ntile + blockIdx.y * gridDim.x + blockIdx.x;
        if (!splitk_finish(cacc, part, cnt, tile, S, bz)) return;
    }
    if (sel == 0)
        gemm_epilogue<2>(cacc, bias, nullptr, C, blockIdx.y * 32, blockIdx.x * 64, EDGE);
    else
        gemm_epilogue<0>(cacc, bias, nullptr, C, blockIdx.y * 32, blockIdx.x * 64, MEM);
}

// ---------------------------------------------------------------------------
// Fused per-row memory block: softmax(logits) -> weights, read, gate, energy.
__global__ void fused_mem_kernel(const float* __restrict__ logits,
                                 const float* __restrict__ memory,
                                 const float* __restrict__ latent,
                                 const float* __restrict__ wg,
                                 const float* __restrict__ wgb,
                                 const float* __restrict__ ew,
                                 const float* __restrict__ eb,
                                 float* __restrict__ weights_out,
                                 float* __restrict__ readv,
                                 float* __restrict__ gate,
                                 float* __restrict__ energy) {
    __shared__ float wsh[SLOTS];
    int b = blockIdx.x;
    int tid = threadIdx.x;

    float x = logits[(size_t)b * SLOTS + tid];
    float m = blockReduceMax(x);
    float e = expf(x - m);
    float ssum = blockReduceSum(e);
    float w = e / ssum;
    weights_out[(size_t)b * SLOTS + tid] = w;
    wsh[tid] = w;
    __syncthreads();

    float4 acc = make_float4(0.f, 0.f, 0.f, 0.f);
    if (tid < MEM / 4) {
        const float4* mb = reinterpret_cast<const float4*>(memory + (size_t)b * SLOTS * MEM);
        #pragma unroll 4
        for (int s = 0; s < SLOTS; s++) {
            float ws = wsh[s];
            float4 mv = mb[(size_t)s * (MEM / 4) + tid];
            acc.x = fmaf(ws, mv.x, acc.x);
            acc.y = fmaf(ws, mv.y, acc.y);
            acc.z = fmaf(ws, mv.z, acc.z);
            acc.w = fmaf(ws, mv.w, acc.w);
        }
        reinterpret_cast<float4*>(readv + (size_t)b * MEM)[tid] = acc;
    }

    float g = 0.0f, en = 0.0f;
    if (tid < MEM / 4) {
        float4 wv = reinterpret_cast<const float4*>(wg + HID)[tid];
        g = acc.x * wv.x + acc.y * wv.y + acc.z * wv.z + acc.w * wv.w;
    }
    const float4* lx = reinterpret_cast<const float4*>(latent + (size_t)b * HID);
    const float4* w1 = reinterpret_cast<const float4*>(wg);
    const float4* ev = reinterpret_cast<const float4*>(ew);
    for (int i = tid; i < HID / 4; i += blockDim.x) {
        float4 xv = lx[i], gv = w1[i], eV = ev[i];
        g  += xv.x * gv.x + xv.y * gv.y + xv.z * gv.z + xv.w * gv.w;
        en += xv.x * eV.x + xv.y * eV.y + xv.z * eV.z + xv.w * eV.w;
    }
    g  = blockReduceSum(g);
    en = blockReduceSum(en);
    if (tid == 0) {
        gate[b]   = sigmoidf_(g + wgb[0]);
        energy[b] = fmaxf(en + eb[0], 0.0f);
    }
}

// new_memory[b,s,d] = m + gate[b]*w[b,s]*(value[b,d] - m), float4 over d
__global__ void newmem_kernel(const float* __restrict__ memory,
                              const float* __restrict__ weights,
                              const float* __restrict__ gate,
                              const float* __restrict__ value,
                              float* __restrict__ out) {
    size_t idx = (size_t)blockIdx.x * blockDim.x + threadIdx.x;  // float4 index
    int b   = (int)(idx >> 15);
    int rem = (int)(idx & 32767);
    int s   = rem >> 7;
    int d4  = rem & 127;
    float gw = gate[b] * weights[(size_t)b * SLOTS + s];
    float4 m = reinterpret_cast<const float4*>(memory)[idx];
    float4 v = reinterpret_cast<const float4*>(value)[(size_t)b * 128 + d4];
    float4 o;
    o.x = fmaf(gw, v.x - m.x, m.x);
    o.y = fmaf(gw, v.y - m.y, m.y);
    o.z = fmaf(gw, v.z - m.z, m.z);
    o.w = fmaf(gw, v.w - m.w, m.w);
    reinterpret_cast<float4*>(out)[idx] = o;
}

// cat[b, 0:512] = refined[b,:], cat[b, 512:544] = remap[b,:]
__global__ void concat_kernel(const float* __restrict__ refined,
                              const float* __restrict__ remap,
                              float* __restrict__ cat) {
    int idx = blockIdx.x * blockDim.x + threadIdx.x;
    if (idx >= BATCH * CATK) return;
    int b = idx / CATK, c = idx - b * CATK;
    cat[idx] = (c < EDGE) ? refined[(size_t)b * EDGE + c]
                          : remap[(size_t)b * GRP + (c - EDGE)];
}

// P = exp(base_map), elementwise
__global__ void expP_kernel(const float* __restrict__ base_map,
                            float* __restrict__ P) {
    int idx = blockIdx.x * blockDim.x + threadIdx.x;
    P[idx] = expf(base_map[idx]);
}

// UV[b,:]     = exp(adapt[b,:] - rowmax)
// UV[512+b,:] = exp(adapt[b,:] - rowmax) * refined[b,:]
__global__ void uv_kernel(const float* __restrict__ adapt,
                          const float* __restrict__ refined,
                          float* __restrict__ UV) {
    int b = blockIdx.x;
    int e = threadIdx.x;          // 512 threads
    float x = adapt[(size_t)b * EDGE + e];
    float m = blockReduceMax(x);
    float u = expf(x - m);
    UV[(size_t)b * EDGE + e] = u;
    UV[(size_t)(BATCH + b) * EDGE + e] = u * refined[(size_t)b * EDGE + e];
}

// io[b,c] = R[512+b,c] / R[b,c]
__global__ void io_kernel(const float* __restrict__ R,
                          float* __restrict__ io) {
    int idx = blockIdx.x * blockDim.x + threadIdx.x;
    int b = idx >> 8, c = idx & 255;
    io[idx] = R[(size_t)(BATCH + b) * IOC + c] / R[(size_t)b * IOC + c];
}

// ---------------------------------------------------------------------------
static inline void gemm_tc(const float* A, const float* W, const float* bias,
                           const float* addend, float* C, float* part, int* cnt,
                           int M, int N, int K, int S, int act) {
    dim3 grid(N / 64, M / 32, S);
    if (act == 0)      gemm_sk_kernel<0><<<grid, 256>>>(A, W, bias, addend, C, part, cnt, M, N, K, S);
    else if (act == 1) gemm_sk_kernel<1><<<grid, 256>>>(A, W, bias, addend, C, part, cnt, M, N, K, S);
    else               gemm_sk_kernel<2><<<grid, 256>>>(A, W, bias, addend, C, part, cnt, M, N, K, S);
}

extern "C" void kernel_launch(void* const* d_in, const int* in_sizes, int n_in,
                              void* d_out, int out_size) {
    const float* signal     = (const float*)d_in[0];
    const float* memory     = (const float*)d_in[1];
    const float* remap_code = (const float*)d_in[2];
    const float* enc_w1     = (const float*)d_in[3];
    const float* enc_b1     = (const float*)d_in[4];
    const float* enc_w2     = (const float*)d_in[5];
    const float* enc_b2     = (const float*)d_in[6];
    const float* edge_w     = (const float*)d_in[7];
    const float* edge_b     = (const float*)d_in[8];
    const float* energy_w   = (const float*)d_in[9];
    const float* energy_b   = (const float*)d_in[10];
    const float* rq_w       = (const float*)d_in[11];
    const float* rq_b       = (const float*)d_in[12];
    const float* wg_w       = (const float*)d_in[13];
    const float* wg_b       = (const float*)d_in[14];
    const float* wv_w       = (const float*)d_in[15];
    const float* wv_b       = (const float*)d_in[16];
    const float* memory_key = (const float*)d_in[17];
    const float* m2e_w      = (const float*)d_in[18];
    const float* m2e_b      = (const float*)d_in[19];
    const float* base_map   = (const float*)d_in[20];
    const float* a1_w       = (const float*)d_in[21];
    const float* a1_b       = (const float*)d_in[22];
    const float* a2_w       = (const float*)d_in[23];
    const float* a2_b       = (const float*)d_in[24];

    float* out = (float*)d_out;
    float* o_latent  = out + OUT_LATENT;
    float* o_refined = out + OUT_REFINED;
    float* o_energy  = out + OUT_ENERGY;
    float* o_io      = out + OUT_IO;
    float* o_newmem  = out + OUT_NEWMEM;
    float* o_weights = out + OUT_WEIGHTS;

    float* scratch = nullptr;
    cudaGetSymbolAddress((void**)&scratch, g_scratch);
    int* cnt = nullptr;
    cudaGetSymbolAddress((void**)&cnt, g_cnt);

    float* lat1      = scratch + OFF_LAT1;
    float* readiness = scratch + OFF_READY;
    float* query     = scratch + OFF_QUERY;
    float* logits    = scratch + OFF_LOGITS;
    float* value     = scratch + OFF_VALUE;
    float* readv     = scratch + OFF_READ;
    float* gate      = scratch + OFF_GATE;
    float* cat       = scratch + OFF_CAT;
    float* hmid      = scratch + OFF_H;
    float* adapt     = scratch + OFF_ADAPT;
    float* UV        = scratch + OFF_UV;
    float* P         = scratch + OFF_P;
    float* R         = scratch + OFF_R;
    float* part      = scratch + OFF_PART;

    // 1-2: encoder (S=2 -> 512 CTAs each)
    gemm_tc(signal, enc_w1, enc_b1, nullptr, lat1,     part, cnt, BATCH, HID, SIG, 2, 1);
    gemm_tc(lat1,   enc_w2, enc_b2, nullptr, o_latent, part, cnt, BATCH, HID, HID, 2, 1);

    // 3: readiness + query + value in ONE launch (S=2 per gemm -> 768 CTAs)
    gemm3_sk_kernel<<<dim3(EDGE / 64, BATCH / 32, 3 * 2), 256>>>(
        o_latent, edge_w, edge_b, rq_w, rq_b, wv_w, wv_b,
        readiness, query, value, part, cnt, 2);

    // 4: logits (S=4 -> 256 CTAs)
    gemm_tc(query, memory_key, nullptr, nullptr, logits, part, cnt, BATCH, SLOTS, MEM, 4, 0);

    // 5: fused softmax/read/gate/energy
    fused_mem_kernel<<<BATCH, 256>>>(logits, memory, o_latent, wg_w, wg_b,
                                     energy_w, energy_b,
                                     o_weights, readv, gate, o_energy);

    // 6: new_memory
    newmem_kernel<<<(BATCH*SLOTS*MEM/4)/256, 256>>>(memory, o_weights, gate, value, o_newmem);

    // 7: refined = sigmoid(readiness + read@m2e^T + m2e_b)  (S=2 -> 256 CTAs)
    gemm_tc(readv, m2e_w, m2e_b, readiness, o_refined, part, cnt, BATCH, EDGE, MEM, 2, 2);

    // 8-10: router MLP (S=2 -> 256 CTAs each; K=544 -> kChunk=272, mult of 16)
    concat_kernel<<<(BATCH*CATK + 255)/256, 256>>>(o_refined, remap_code, cat);
    gemm_tc(cat,  a1_w, a1_b, nullptr, hmid,  part, cnt, BATCH, EDGE, CATK, 2, 1);
    gemm_tc(hmid, a2_w, a2_b, nullptr, adapt, part, cnt, BATCH, EDGE, EDGE, 2, 0);

    // 11-14: factorized io softmax (R GEMM S=2 -> 256 CTAs)
    expP_kernel<<<(IOC*EDGE)/256, 256>>>(base_map, P);
    uv_kernel<<<BATCH, EDGE>>>(adapt, o_refined, UV);
    gemm_tc(UV, P, nullptr, nullptr, R, part, cnt, 2*BATCH, IOC, EDGE, 2, 0);
    io_kernel<<<(BATCH*IOC)/256, 256>>>(R, o_io);
}

// round 13
// speedup vs baseline: 1.2846x; 1.2312x over previous
#include <cuda_runtime.h>
#include <cuda_bf16.h>
#include <math.h>

// Shapes
#define BATCH 512
#define SIG   512
#define HID   1024
#define EDGE  512
#define SLOTS 256
#define MEM   512
#define IOC   256
#define GRP   32
#define CATK  544

// ---------------- fp32 scratch ----------------
#define OFF_READY  0
#define OFF_LOGITS 262144
#define OFF_VALUE  393216
#define OFF_GATE   655360
#define OFF_ADAPT  655872
#define OFF_R      918016
#define OFF_PART   1180160           // 2,097,152 floats of split-K partials
#define SCR_FLOATS (OFF_PART + 2097152)
__device__ float g_scratch[SCR_FLOATS];

// ---------------- packed bf16 hi/lo planes (u32 words; hi plane then lo) ----
// words = rows * K/2 per plane; buffer block = 2*words
#define BW_ENC1 0u        // 1024x512  -> 262144
#define BW_ENC2 524288u   // 1024x1024 -> 524288
#define BW_EDGE 1572864u  // 512x1024  -> 262144
#define BW_RQ   2097152u
#define BW_WV   2621440u
#define BW_MK   3145728u  // 256x512   -> 65536
#define BW_M2E  3276800u  // 512x512   -> 131072
#define BW_A1   3538944u  // 512x544   -> 139264
#define BW_A2   3817472u  // 512x512   -> 131072
#define BW_SIG  4079616u  // 512x512   -> 131072
#define BW_LAT1 4341760u  // 512x1024  -> 262144
#define BW_LAT  4866048u  // 512x1024  -> 262144
#define BW_Q    5390336u  // 512x512   -> 131072
#define BW_READ 5652480u  // 512x512   -> 131072
#define BW_CAT  5914624u  // 512x544   -> 139264
#define BW_HMID 6193152u  // 512x512   -> 131072
#define BW_UV   6455296u  // 1024x512  -> 262144
#define BW_P    6979584u  // 256x512   -> 65536
#define BF16_WORDS 7110656
__device__ unsigned g_bf16[BF16_WORDS];

// Output layout (flat concat, reference return order)
#define OUT_LATENT  0
#define OUT_REFINED 524288
#define OUT_ENERGY  786432
#define OUT_IO      786944
#define OUT_NEWMEM  918016
#define OUT_WEIGHTS 68026880

// ---------------------------------------------------------------------------
__device__ __forceinline__ float sigmoidf_(float x) { return 1.0f / (1.0f + expf(-x)); }
__device__ __forceinline__ float siluf_(float x)    { return x / (1.0f + expf(-x)); }

__device__ __forceinline__ void bf16hl_pack(float x0, float x1, unsigned& hi, unsigned& lo) {
    __nv_bfloat16 h0 = __float2bfloat16_rn(x0);
    __nv_bfloat16 h1 = __float2bfloat16_rn(x1);
    hi = ((unsigned)__bfloat16_as_ushort(h1) << 16) | (unsigned)__bfloat16_as_ushort(h0);
    float r0 = x0 - __bfloat162float(h0);
    float r1 = x1 - __bfloat162float(h1);
    __nv_bfloat16 l0 = __float2bfloat16_rn(r0);
    __nv_bfloat16 l1 = __float2bfloat16_rn(r1);
    lo = ((unsigned)__bfloat16_as_ushort(l1) << 16) | (unsigned)__bfloat16_as_ushort(l0);
}

__device__ __forceinline__ float blockReduceSum(float v) {
    __shared__ float sh[33];
    __syncthreads();
    int lane = threadIdx.x & 31, wid = threadIdx.x >> 5;
    #pragma unroll
    for (int o = 16; o > 0; o >>= 1) v += __shfl_down_sync(0xffffffffu, v, o);
    if (lane == 0) sh[wid] = v;
    __syncthreads();
    int nw = (blockDim.x + 31) >> 5;
    if (wid == 0) {
        float w = (lane < nw) ? sh[lane] : 0.0f;
        #pragma unroll
        for (int o = 16; o > 0; o >>= 1) w += __shfl_down_sync(0xffffffffu, w, o);
        if (lane == 0) sh[32] = w;
    }
    __syncthreads();
    return sh[32];
}

__device__ __forceinline__ float blockReduceMax(float v) {
    __shared__ float sh[33];
    __syncthreads();
    int lane = threadIdx.x & 31, wid = threadIdx.x >> 5;
    #pragma unroll
    for (int o = 16; o > 0; o >>= 1) v = fmaxf(v, __shfl_down_sync(0xffffffffu, v, o));
    if (lane == 0) sh[wid] = v;
    __syncthreads();
    int nw = (blockDim.x + 31) >> 5;
    if (wid == 0) {
        float w = (lane < nw) ? sh[lane] : -3.4e38f;
        #pragma unroll
        for (int o = 16; o > 0; o >>= 1) w = fmaxf(w, __shfl_down_sync(0xffffffffu, w, o));
        if (lane == 0) sh[32] = w;
    }
    __syncthreads();
    return sh[32];
}

// ---------------------------------------------------------------------------
// Input conversion: fp32 -> packed bf16 hi/lo planes. One launch, all inputs.
struct CvtTab {
    const float* src[10];
    unsigned dstoff[10];   // hi plane word offset into g_bf16
    unsigned words[10];    // words per plane (lo at dstoff+words)
    unsigned cum[11];
};

__global__ void convert_kernel(CvtTab t, int total) {
    int w = blockIdx.x * blockDim.x + threadIdx.x;
    if (w >= total) return;
    int k = 0;
    while (w >= (int)t.cum[k + 1]) k++;
    unsigned p = w - t.cum[k];
    float2 v = reinterpret_cast<const float2*>(t.src[k])[p];
    unsigned hi, lo;
    bf16hl_pack(v.x, v.y, hi, lo);
    g_bf16[t.dstoff[k] + p] = hi;
    g_bf16[t.dstoff[k] + t.words[k] + p] = lo;
}

// ---------------------------------------------------------------------------
// bf16x3 GEMM core. CTA tile 64x64, BK=16 elems (8 packed words), 128 threads,
// 4 warps (2x2), each warp 32x32 via 2x4 m16n8k16 atoms, 3 passes
// (hi*hi + hi*lo + lo*hi). Operands read from packed bf16 hi/lo planes.
__device__ __forceinline__ void mma_bf16(float c[4], const unsigned a[4], const unsigned b[2]) {
    asm("mma.sync.aligned.m16n8k16.row.col.f32.bf16.bf16.f32 "
        "{%0,%1,%2,%3}, {%4,%5,%6,%7}, {%8,%9}, {%0,%1,%2,%3};\n"
        : "+f"(c[0]), "+f"(c[1]), "+f"(c[2]), "+f"(c[3])
        : "r"(a[0]), "r"(a[1]), "r"(a[2]), "r"(a[3]), "r"(b[0]), "r"(b[1]));
}

#define SPITCH 12   // words per smem row (8 data + 4 pad) -> conflict-free fragments

__device__ __forceinline__ void bf16_core(unsigned* sm,
                                          const unsigned* __restrict__ Ahi,
                                          const unsigned* __restrict__ Alo,
                                          const unsigned* __restrict__ Whi,
                                          const unsigned* __restrict__ Wlo,
                                          int byM, int bxN, int K2,
                                          int kw0, int kwLen,
                                          float cacc[2][4][4]) {
    unsigned* AhP = sm;
    unsigned* AlP = sm + 768;
    unsigned* BhP = sm + 1536;
    unsigned* BlP = sm + 2304;

    const int tid = threadIdx.x;
    const int lane = tid & 31;
    const int warp = tid >> 5;
    const int wm = (warp >> 1) << 5;
    const int wn = (warp & 1) << 5;
    const int r4 = lane >> 2;
    const int c4 = lane & 3;

    const int arow = tid >> 1;           // 0..63
    const int ah4  = (tid & 1) << 2;     // 0 or 4
    const int sa   = arow * SPITCH + ah4;

    const unsigned* pAh = Ahi + (size_t)(byM + arow) * K2 + kw0 + ah4;
    const unsigned* pAl = Alo + (size_t)(byM + arow) * K2 + kw0 + ah4;
    const unsigned* pBh = Whi + (size_t)(bxN + arow) * K2 + kw0 + ah4;
    const unsigned* pBl = Wlo + (size_t)(bxN + arow) * K2 + kw0 + ah4;

    #pragma unroll
    for (int mi = 0; mi < 2; mi++)
        #pragma unroll
        for (int ni = 0; ni < 4; ni++)
            #pragma unroll
            for (int r = 0; r < 4; r++) cacc[mi][ni][r] = 0.0f;

    uint4 vah = *reinterpret_cast<const uint4*>(pAh);
    uint4 val = *reinterpret_cast<const uint4*>(pAl);
    uint4 vbh = *reinterpret_cast<const uint4*>(pBh);
    uint4 vbl = *reinterpret_cast<const uint4*>(pBl);

    for (int kt = 0; kt < kwLen; kt += 8) {
        *reinterpret_cast<uint4*>(AhP + sa) = vah;
        *reinterpret_cast<uint4*>(AlP + sa) = val;
        *reinterpret_cast<uint4*>(BhP + sa) = vbh;
        *reinterpret_cast<uint4*>(BlP + sa) = vbl;
        __syncthreads();

        if (kt + 8 < kwLen) {            // prefetch next k-tile
            vah = *reinterpret_cast<const uint4*>(pAh + kt + 8);
            val = *reinterpret_cast<const uint4*>(pAl + kt + 8);
            vbh = *reinterpret_cast<const uint4*>(pBh + kt + 8);
            vbl = *reinterpret_cast<const uint4*>(pBl + kt + 8);
        }

        unsigned ah[2][4], al[2][4], bh[4][2], bl[4][2];
        #pragma unroll
        for (int mi = 0; mi < 2; mi++) {
            int mb = wm + mi * 16;
            ah[mi][0] = AhP[(mb + r4    ) * SPITCH + c4    ];
            ah[mi][1] = AhP[(mb + r4 + 8) * SPITCH + c4    ];
            ah[mi][2] = AhP[(mb + r4    ) * SPITCH + c4 + 4];
            ah[mi][3] = AhP[(mb + r4 + 8) * SPITCH + c4 + 4];
            al[mi][0] = AlP[(mb + r4    ) * SPITCH + c4    ];
            al[mi][1] = AlP[(mb + r4 + 8) * SPITCH + c4    ];
            al[mi][2] = AlP[(mb + r4    ) * SPITCH + c4 + 4];
            al[mi][3] = AlP[(mb + r4 + 8) * SPITCH + c4 + 4];
        }
        #pragma unroll
        for (int ni = 0; ni < 4; ni++) {
            int nb = wn + ni * 8 + r4;
            bh[ni][0] = BhP[nb * SPITCH + c4    ];
            bh[ni][1] = BhP[nb * SPITCH + c4 + 4];
            bl[ni][0] = BlP[nb * SPITCH + c4    ];
            bl[ni][1] = BlP[nb * SPITCH + c4 + 4];
        }
        // pass 1: hi*hi  (8 independent accumulators)
        #pragma unroll
        for (int mi = 0; mi < 2; mi++)
            #pragma unroll
            for (int ni = 0; ni < 4; ni++) mma_bf16(cacc[mi][ni], ah[mi], bh[ni]);
        // pass 2: hi*lo
        #pragma unroll
        for (int mi = 0; mi < 2; mi++)
            #pragma unroll
            for (int ni = 0; ni < 4; ni++) mma_bf16(cacc[mi][ni], ah[mi], bl[ni]);
        // pass 3: lo*hi
        #pragma unroll
        for (int mi = 0; mi < 2; mi++)
            #pragma unroll
            for (int ni = 0; ni < 4; ni++) mma_bf16(cacc[mi][ni], al[mi], bh[ni]);
        __syncthreads();
    }
}

__device__ __forceinline__ void store_partial(const float cacc[2][4][4],
                                              float* __restrict__ Cp,
                                              int byM, int bxN, int N) {
    const int lane = threadIdx.x & 31;
    const int warp = threadIdx.x >> 5;
    const int wm = (warp >> 1) << 5;
    const int wn = (warp & 1) << 5;
    const int r4 = lane >> 2;
    const int c4 = lane & 3;
    #pragma unroll
    for (int mi = 0; mi < 2; mi++) {
        #pragma unroll
        for (int ni = 0; ni < 4; ni++) {
            int col0 = bxN + wn + ni * 8 + c4 * 2;
            #pragma unroll
            for (int half = 0; half < 2; half++) {
                int row = byM + wm + mi * 16 + r4 + half * 8;
                *reinterpret_cast<float2*>(Cp + (size_t)row * N + col0) =
                    make_float2(cacc[mi][ni][half * 2 + 0], cacc[mi][ni][half * 2 + 1]);
            }
        }
    }
}

__global__ void __launch_bounds__(128, 4)
gemm_bf16_kernel(const unsigned* __restrict__ Ahi, const unsigned* __restrict__ Alo,
                 const unsigned* __restrict__ Whi, const unsigned* __restrict__ Wlo,
                 float* __restrict__ part, int M, int N, int K2, int S) {
    __shared__ unsigned sm[3072];
    float cacc[2][4][4];
    int kw = K2 / S;
    bf16_core(sm, Ahi, Alo, Whi, Wlo, blockIdx.y * 64, blockIdx.x * 64, K2,
              blockIdx.z * kw, kw, cacc);
    store_partial(cacc, part + (size_t)blockIdx.z * M * N, blockIdx.y * 64, blockIdx.x * 64, N);
}

// trio: A=latent, K=1024 (K2=512), S=2 per gemm; blockIdx.z = sel*2 + bz
__global__ void __launch_bounds__(128, 4)
gemm3_bf16_kernel(const unsigned* __restrict__ Ahi, const unsigned* __restrict__ Alo,
                  const unsigned* __restrict__ eWhi, const unsigned* __restrict__ eWlo,
                  const unsigned* __restrict__ qWhi, const unsigned* __restrict__ qWlo,
                  const unsigned* __restrict__ vWhi, const unsigned* __restrict__ vWlo,
                  float* __restrict__ part) {
    __shared__ unsigned sm[3072];
    float cacc[2][4][4];
    int sel = blockIdx.z >> 1;
    int bz  = blockIdx.z & 1;
    const unsigned *Whi, *Wlo;
    if (sel == 0)      { Whi = eWhi; Wlo = eWlo; }
    else if (sel == 1) { Whi = qWhi; Wlo = qWlo; }
    else               { Whi = vWhi; Wlo = vWlo; }
    bf16_core(sm, Ahi, Alo, Whi, Wlo, blockIdx.y * 64, blockIdx.x * 64, 512,
              bz * 256, 256, cacc);
    store_partial(cacc, part + (size_t)(sel * 2 + bz) * (512 * 512),
                  blockIdx.y * 64, blockIdx.x * 64, 512);
}

// ---------------------------------------------------------------------------
// Split-K reduce + fused epilogue. Emits fp32 and/or packed bf16 hi/lo.
__device__ __forceinline__ void reduce_impl(int i4, const float* __restrict__ part,
                                            int S, int MN4, int N,
                                            const float* __restrict__ bias,
                                            const float* __restrict__ addend,
                                            int act,
                                            float* __restrict__ outF,
                                            unsigned* __restrict__ outHi,
                                            unsigned* __restrict__ outLo) {
    const float4* p4 = reinterpret_cast<const float4*>(part);
    float4 s = p4[i4];
    for (int z = 1; z < S; z++) {
        float4 t = p4[(size_t)z * MN4 + i4];
        s.x += t.x; s.y += t.y; s.z += t.z; s.w += t.w;
    }
    int col = (i4 & (N / 4 - 1)) << 2;   // N is a power of two here
    if (bias) {
        s.x += bias[col + 0]; s.y += bias[col + 1];
        s.z += bias[col + 2]; s.w += bias[col + 3];
    }
    if (addend) {
        float4 t = reinterpret_cast<const float4*>(addend)[i4];
        s.x += t.x; s.y += t.y; s.z += t.z; s.w += t.w;
    }
    if (act == 1) { s.x = siluf_(s.x); s.y = siluf_(s.y); s.z = siluf_(s.z); s.w = siluf_(s.w); }
    if (act == 2) { s.x = sigmoidf_(s.x); s.y = sigmoidf_(s.y); s.z = sigmoidf_(s.z); s.w = sigmoidf_(s.w); }
    if (outF) reinterpret_cast<float4*>(outF)[i4] = s;
    if (outHi) {
        unsigned h01, l01, h23, l23;
        bf16hl_pack(s.x, s.y, h01, l01);
        bf16hl_pack(s.z, s.w, h23, l23);
        reinterpret_cast<uint2*>(outHi)[i4] = make_uint2(h01, h23);
        reinterpret_cast<uint2*>(outLo)[i4] = make_uint2(l01, l23);
    }
}

__global__ void reduce_kernel(const float* __restrict__ part, int S, int MN4, int N,
                              const float* __restrict__ bias,
                              const float* __restrict__ addend, int act,
                              float* __restrict__ outF,
                              unsigned* __restrict__ outHi,
                              unsigned* __restrict__ outLo) {
    int i4 = blockIdx.x * blockDim.x + threadIdx.x;
    if (i4 >= MN4) return;
    reduce_impl(i4, part, S, MN4, N, bias, addend, act, outF, outHi, outLo);
}

// trio reduce: z=0 readiness(sigmoid,f32), z=1 query(bf16hl), z=2 value(f32)
__global__ void reduce3_kernel(const float* __restrict__ part, int MN4,
                               const float* __restrict__ edge_b,
                               const float* __restrict__ rq_b,
                               const float* __restrict__ wv_b,
                               float* __restrict__ readiness,
                               unsigned* __restrict__ qHi, unsigned* __restrict__ qLo,
                               float* __restrict__ value) {
    int i4 = blockIdx.x * blockDim.x + threadIdx.x;
    if (i4 >= MN4) return;
    int sel = blockIdx.z;
    const float* p = part + (size_t)sel * 2 * MN4 * 4;
    if (sel == 0)      reduce_impl(i4, p, 2, MN4, EDGE, edge_b, nullptr, 2, readiness, nullptr, nullptr);
    else if (sel == 1) reduce_impl(i4, p, 2, MN4, MEM, rq_b, nullptr, 0, nullptr, qHi, qLo);
    else               reduce_impl(i4, p, 2, MN4, MEM, wv_b, nullptr, 0, value, nullptr, nullptr);
}

// ---------------------------------------------------------------------------
// Fused: softmax(logits)->weights, read (emitted bf16hl), gate, energy.
__global__ void fused_mem_kernel(const float* __restrict__ logits,
                                 const float* __restrict__ memory,
                                 const float* __restrict__ latent,
                                 const float* __restrict__ wg,
                                 const float* __restrict__ wgb,
                                 const float* __restrict__ ew,
                                 const float* __restrict__ eb,
                                 float* __restrict__ weights_out,
                                 unsigned* __restrict__ readHi,
                                 unsigned* __restrict__ readLo,
                                 float* __restrict__ gate,
                                 float* __restrict__ energy) {
    __shared__ float wsh[SLOTS];
    int b = blockIdx.x;
    int tid = threadIdx.x;

    float x = logits[(size_t)b * SLOTS + tid];
    float m = blockReduceMax(x);
    float e = expf(x - m);
    float ssum = blockReduceSum(e);
    float w = e / ssum;
    weights_out[(size_t)b * SLOTS + tid] = w;
    wsh[tid] = w;
    __syncthreads();

    float4 acc = make_float4(0.f, 0.f, 0.f, 0.f);
    if (tid < MEM / 4) {
        const float4* mb = reinterpret_cast<const float4*>(memory + (size_t)b * SLOTS * MEM);
        #pragma unroll 4
        for (int s = 0; s < SLOTS; s++) {
            float ws = wsh[s];
            float4 mv = mb[(size_t)s * (MEM / 4) + tid];
            acc.x = fmaf(ws, mv.x, acc.x);
            acc.y = fmaf(ws, mv.y, acc.y);
            acc.z = fmaf(ws, mv.z, acc.z);
            acc.w = fmaf(ws, mv.w, acc.w);
        }
        unsigned h0, l0, h1, l1;
        bf16hl_pack(acc.x, acc.y, h0, l0);
        bf16hl_pack(acc.z, acc.w, h1, l1);
        reinterpret_cast<uint2*>(readHi + (size_t)b * (MEM / 2))[tid] = make_uint2(h0, h1);
        reinterpret_cast<uint2*>(readLo + (size_t)b * (MEM / 2))[tid] = make_uint2(l0, l1);
    }

    float g = 0.0f, en = 0.0f;
    if (tid < MEM / 4) {
        float4 wv = reinterpret_cast<const float4*>(wg + HID)[tid];
        g = acc.x * wv.x + acc.y * wv.y + acc.z * wv.z + acc.w * wv.w;
    }
    const float4* lx = reinterpret_cast<const float4*>(latent + (size_t)b * HID);
    const float4* w1 = reinterpret_cast<const float4*>(wg);
    const float4* ev = reinterpret_cast<const float4*>(ew);
    for (int i = tid; i < HID / 4; i += blockDim.x) {
        float4 xv = lx[i], gv = w1[i], eV = ev[i];
        g  += xv.x * gv.x + xv.y * gv.y + xv.z * gv.z + xv.w * gv.w;
        en += xv.x * eV.x + xv.y * eV.y + xv.z * eV.z + xv.w * eV.w;
    }
    g  = blockReduceSum(g);
    en = blockReduceSum(en);
    if (tid == 0) {
        gate[b]   = sigmoidf_(g + wgb[0]);
        energy[b] = fmaxf(en + eb[0], 0.0f);
    }
}

// new_memory[b,s,d] = m + gate[b]*w[b,s]*(value[b,d] - m), float4 over d
__global__ void newmem_kernel(const float* __restrict__ memory,
                              const float* __restrict__ weights,
                              const float* __restrict__ gate,
                              const float* __restrict__ value,
                              float* __restrict__ out) {
    size_t idx = (size_t)blockIdx.x * blockDim.x + threadIdx.x;
    int b   = (int)(idx >> 15);
    int rem = (int)(idx & 32767);
    int s   = rem >> 7;
    int d4  = rem & 127;
    float gw = gate[b] * weights[(size_t)b * SLOTS + s];
    float4 m = reinterpret_cast<const float4*>(memory)[idx];
    float4 v = reinterpret_cast<const float4*>(value)[(size_t)b * 128 + d4];
    float4 o;
    o.x = fmaf(gw, v.x - m.x, m.x);
    o.y = fmaf(gw, v.y - m.y, m.y);
    o.z = fmaf(gw, v.z - m.z, m.z);
    o.w = fmaf(gw, v.w - m.w, m.w);
    reinterpret_cast<float4*>(out)[idx] = o;
}

// cat (bf16hl) = [refined | remap], word-granular (2 elems per thread)
__global__ void concat_kernel(const float* __restrict__ refined,
                              const float* __restrict__ remap,
                              unsigned* __restrict__ cHi, unsigned* __restrict__ cLo) {
    int w = blockIdx.x * blockDim.x + threadIdx.x;
    if (w >= BATCH * (CATK / 2)) return;
    int b = w / (CATK / 2), wc = w - b * (CATK / 2);
    int c = wc * 2;
    float v0, v1;
    if (c < EDGE) { v0 = refined[(size_t)b * EDGE + c]; v1 = refined[(size_t)b * EDGE + c + 1]; }
    else { v0 = remap[(size_t)b * GRP + (c - EDGE)]; v1 = remap[(size_t)b * GRP + (c - EDGE) + 1]; }
    unsigned hi, lo;
    bf16hl_pack(v0, v1, hi, lo);
    cHi[w] = hi;
    cLo[w] = lo;
}

// P = exp(base_map) emitted bf16hl
__global__ void expP_kernel(const float* __restrict__ base_map,
                            unsigned* __restrict__ pHi, unsigned* __restrict__ pLo) {
    int w = blockIdx.x * blockDim.x + threadIdx.x;   // IOC*EDGE/2 = 65536 words
    float2 v = reinterpret_cast<const float2*>(base_map)[w];
    unsigned hi, lo;
    bf16hl_pack(expf(v.x), expf(v.y), hi, lo);
    pHi[w] = hi;
    pLo[w] = lo;
}

// UV rows b (exp(adapt-max)) and BATCH+b (times refined), emitted bf16hl
__global__ void uv_kernel(const float* __restrict__ adapt,
                          const float* __restrict__ refined,
                          unsigned* __restrict__ uvHi, unsigned* __restrict__ uvLo) {
    int b = blockIdx.x;
    int t = threadIdx.x;   // 256 threads, 2 elems each
    float2 x = reinterpret_cast<const float2*>(adapt + (size_t)b * EDGE)[t];
    float m = blockReduceMax(fmaxf(x.x, x.y));
    float u0 = expf(x.x - m), u1 = expf(x.y - m);
    unsigned hi, lo;
    bf16hl_pack(u0, u1, hi, lo);
    uvHi[(size_t)b * 256 + t] = hi;
    uvLo[(size_t)b * 256 + t] = lo;
    float2 rf = reinterpret_cast<const float2*>(refined + (size_t)b * EDGE)[t];
    bf16hl_pack(u0 * rf.x, u1 * rf.y, hi, lo);
    uvHi[(size_t)(BATCH + b) * 256 + t] = hi;
    uvLo[(size_t)(BATCH + b) * 256 + t] = lo;
}

// io[b,c] = R[512+b,c] / R[b,c]
__global__ void io_kernel(const float* __restrict__ R, float* __restrict__ io) {
    int idx = blockIdx.x * blockDim.x + threadIdx.x;
    int b = idx >> 8, c = idx & 255;
    io[idx] = R[(size_t)(BATCH + b) * IOC + c] / R[(size_t)b * IOC + c];
}

// ---------------------------------------------------------------------------
extern "C" void kernel_launch(void* const* d_in, const int* in_sizes, int n_in,
                              void* d_out, int out_size) {
    const float* signal     = (const float*)d_in[0];
    const float* memory     = (const float*)d_in[1];
    const float* remap_code = (const float*)d_in[2];
    const float* enc_w1     = (const float*)d_in[3];
    const float* enc_b1     = (const float*)d_in[4];
    const float* enc_w2     = (const float*)d_in[5];
    const float* enc_b2     = (const float*)d_in[6];
    const float* edge_w     = (const float*)d_in[7];
    const float* edge_b     = (const float*)d_in[8];
    const float* energy_w   = (const float*)d_in[9];
    const float* energy_b   = (const float*)d_in[10];
    const float* rq_w       = (const float*)d_in[11];
    const float* rq_b       = (const float*)d_in[12];
    const float* wg_w       = (const float*)d_in[13];
    const float* wg_b       = (const float*)d_in[14];
    const float* wv_w       = (const float*)d_in[15];
    const float* wv_b       = (const float*)d_in[16];
    const float* memory_key = (const float*)d_in[17];
    const float* m2e_w      = (const float*)d_in[18];
    const float* m2e_b      = (const float*)d_in[19];
    const float* base_map   = (const float*)d_in[20];
    const float* a1_w       = (const float*)d_in[21];
    const float* a1_b       = (const float*)d_in[22];
    const float* a2_w       = (const float*)d_in[23];
    const float* a2_b       = (const float*)d_in[24];

    float* out = (float*)d_out;
    float* o_latent  = out + OUT_LATENT;
    float* o_refined = out + OUT_REFINED;
    float* o_energy  = out + OUT_ENERGY;
    float* o_io      = out + OUT_IO;
    float* o_newmem  = out + OUT_NEWMEM;
    float* o_weights = out + OUT_WEIGHTS;

    float* scratch = nullptr;
    cudaGetSymbolAddress((void**)&scratch, g_scratch);
    unsigned* bf = nullptr;
    cudaGetSymbolAddress((void**)&bf, g_bf16);

    float* readiness = scratch + OFF_READY;
    float* logits    = scratch + OFF_LOGITS;
    float* value     = scratch + OFF_VALUE;
    float* gate      = scratch + OFF_GATE;
    float* adapt     = scratch + OFF_ADAPT;
    float* Rbuf      = scratch + OFF_R;
    float* part      = scratch + OFF_PART;

    // 0: convert all fp32 GEMM inputs (weights + signal + memory_key) to bf16 hi/lo
    CvtTab t;
    const float* srcs[10] = {enc_w1, enc_w2, edge_w, rq_w, wv_w,
                             memory_key, m2e_w, a1_w, a2_w, signal};
    unsigned offs[10] = {BW_ENC1, BW_ENC2, BW_EDGE, BW_RQ, BW_WV,
                         BW_MK, BW_M2E, BW_A1, BW_A2, BW_SIG};
    unsigned wrds[10] = {262144, 524288, 262144, 262144, 262144,
                         65536, 131072, 139264, 131072, 131072};
    unsigned cum = 0;
    for (int i = 0; i < 10; i++) {
        t.src[i] = srcs[i]; t.dstoff[i] = offs[i]; t.words[i] = wrds[i];
        t.cum[i] = cum; cum += wrds[i];
    }
    t.cum[10] = cum;
    convert_kernel<<<(cum + 255) / 256, 256>>>(t, (int)cum);

    // 1: enc1  lat1 = silu(signal@enc_w1^T+b)  (bf16hl only)
    gemm_bf16_kernel<<<dim3(16, 8, 2), 128>>>(bf + BW_SIG, bf + BW_SIG + 131072,
                                              bf + BW_ENC1, bf + BW_ENC1 + 262144,
                                              part, BATCH, HID, 256, 2);
    reduce_kernel<<<512, 256>>>(part, 2, 131072, HID, enc_b1, nullptr, 1,
                                nullptr, bf + BW_LAT1, bf + BW_LAT1 + 262144);

    // 2: enc2  latent (fp32 output + bf16hl)
    gemm_bf16_kernel<<<dim3(16, 8, 2), 128>>>(bf + BW_LAT1, bf + BW_LAT1 + 262144,
                                              bf + BW_ENC2, bf + BW_ENC2 + 524288,
                                              part, BATCH, HID, 512, 2);
    reduce_kernel<<<512, 256>>>(part, 2, 131072, HID, enc_b2, nullptr, 1,
                                o_latent, bf + BW_LAT, bf + BW_LAT + 262144);

    // 3: trio readiness/query/value (one gemm launch + one reduce launch)
    gemm3_bf16_kernel<<<dim3(8, 8, 6), 128>>>(bf + BW_LAT, bf + BW_LAT + 262144,
                                              bf + BW_EDGE, bf + BW_EDGE + 262144,
                                              bf + BW_RQ, bf + BW_RQ + 262144,
                                              bf + BW_WV, bf + BW_WV + 262144,
                                              part);
    reduce3_kernel<<<dim3(256, 1, 3), 256>>>(part, 65536, edge_b, rq_b, wv_b,
                                             readiness, bf + BW_Q, bf + BW_Q + 131072, value);

    // 4: logits = query @ memory_key^T  (fp32)
    gemm_bf16_kernel<<<dim3(4, 8, 8), 128>>>(bf + BW_Q, bf + BW_Q + 131072,
                                             bf + BW_MK, bf + BW_MK + 65536,
                                             part, BATCH, SLOTS, 256, 8);
    reduce_kernel<<<128, 256>>>(part, 8, 32768, SLOTS, nullptr, nullptr, 0,
                                logits, nullptr, nullptr);

    // 5: fused softmax/read/gate/energy (read emitted bf16hl)
    fused_mem_kernel<<<BATCH, 256>>>(logits, memory, o_latent, wg_w, wg_b,
                                     energy_w, energy_b, o_weights,
                                     bf + BW_READ, bf + BW_READ + 131072,
                                     gate, o_energy);

    // 6: new_memory
    newmem_kernel<<<(BATCH * SLOTS * MEM / 4) / 256, 256>>>(memory, o_weights, gate,
                                                            value, o_newmem);

    // 7: refined = sigmoid(readiness + read@m2e^T + b)  (fp32 output)
    gemm_bf16_kernel<<<dim3(8, 8, 4), 128>>>(bf + BW_READ, bf + BW_READ + 131072,
                                             bf + BW_M2E, bf + BW_M2E + 131072,
                                             part, BATCH, EDGE, 256, 4);
    reduce_kernel<<<256, 256>>>(part, 4, 65536, EDGE, m2e_b, readiness, 2,
                                o_refined, nullptr, nullptr);

    // 8-10: router MLP
    concat_kernel<<<(BATCH * (CATK / 2) + 255) / 256, 256>>>(o_refined, remap_code,
                                                             bf + BW_CAT, bf + BW_CAT + 139264);
    gemm_bf16_kernel<<<dim3(8, 8, 2), 128>>>(bf + BW_CAT, bf + BW_CAT + 139264,
                                             bf + BW_A1, bf + BW_A1 + 139264,
                                             part, BATCH, EDGE, 272, 2);
    reduce_kernel<<<256, 256>>>(part, 2, 65536, EDGE, a1_b, nullptr, 1,
                                nullptr, bf + BW_HMID, bf + BW_HMID + 131072);
    gemm_bf16_kernel<<<dim3(8, 8, 4), 128>>>(bf + BW_HMID, bf + BW_HMID + 131072,
                                             bf + BW_A2, bf + BW_A2 + 131072,
                                             part, BATCH, EDGE, 256, 4);
    reduce_kernel<<<256, 256>>>(part, 4, 65536, EDGE, a2_b, nullptr, 0,
                                adapt, nullptr, nullptr);

    // 11-14: factorized io softmax via two bf16 GEMM operands P, UV
    expP_kernel<<<(IOC * EDGE / 2) / 256, 256>>>(base_map, bf + BW_P, bf + BW_P + 65536);
    uv_kernel<<<BATCH, 256>>>(adapt, o_refined, bf + BW_UV, bf + BW_UV + 262144);
    gemm_bf16_kernel<<<dim3(4, 16, 4), 128>>>(bf + BW_UV, bf + BW_UV + 262144,
                                              bf + BW_P, bf + BW_P + 65536,
                                              part, 2 * BATCH, IOC, 256, 4);
    reduce_kernel<<<256, 256>>>(part, 4, 65536, IOC, nullptr, nullptr, 0,
                                Rbuf, nullptr, nullptr);
    io_kernel<<<(BATCH * IOC) / 256, 256>>>(Rbuf, o_io);
}